// round 4
// baseline (speedup 1.0000x reference)
#include <cuda_runtime.h>

#define B_ 8
#define C_ 256
#define N_ 1024
#define K_ 16
#define CQ_ 64
#define BK_ (B_*K_)
#define MALL 640
#define NELEM_T ((size_t)BK_*C_*N_)

// ---------------- scratch (device globals; no allocation allowed) ----------------
__device__ float g_wall[MALL*C_];                 // stacked weights [640,256]
__device__ float g_ball[MALL];                    // stacked biases
__device__ float g_xt[NELEM_T];                   // x transposed [B,K,C,N]
__device__ float g_q[(size_t)BK_*CQ_*N_];         // [B,K,CQ,N]
__device__ float g_k[(size_t)BK_*CQ_*N_];         // [B,K,CQ,N]
__device__ float g_u[NELEM_T];                    // (t_w@v_w)@x + t_w@v_b   [B,K,C,N]
__device__ float g_t1[NELEM_T];                   // t_w@x + t_b             [B,K,C,N]
__device__ float g_t[NELEM_T];                    // t = t1 - u@attn         [B,K,C,N]
__device__ float g_e[(size_t)BK_*N_*N_];          // energy / attn  [B,K,N,N]  537 MB
__device__ float g_mean[C_];
__device__ float g_rstd[C_];

// ---------------- 0: fold weights:  W2 = t_w@v_w, c0 = t_w@v_b, stack ----------------
__global__ void k_prep(const float* __restrict__ qw, const float* __restrict__ kw,
                       const float* __restrict__ vw, const float* __restrict__ vb,
                       const float* __restrict__ tw, const float* __restrict__ tb) {
    int r = blockIdx.x, c = threadIdx.x;
    if (r < 64) {
        g_wall[r*C_+c] = qw[r*C_+c];
        if (c == 0) g_ball[r] = 0.f;
    } else if (r < 128) {
        g_wall[r*C_+c] = kw[(r-64)*C_+c];
        if (c == 0) g_ball[r] = 0.f;
    } else if (r < 384) {
        int o = r - 128;
        float s = 0.f;
        for (int c2 = 0; c2 < C_; c2++) s = fmaf(tw[o*C_+c2], vw[c2*C_+c], s);
        g_wall[r*C_+c] = s;
        if (c == 0) {
            float sb = 0.f;
            for (int c2 = 0; c2 < C_; c2++) sb = fmaf(tw[o*C_+c2], vb[c2], sb);
            g_ball[r] = sb;
        }
    } else {
        int o = r - 384;
        g_wall[r*C_+c] = tw[o*C_+c];
        if (c == 0) g_ball[r] = tb[o];
    }
}

// ---------------- 1: transpose x [B,C,N,K] -> xt [B,K,C,N] ----------------
__global__ void k_xpose(const float* __restrict__ x) {
    __shared__ float s[64][17];
    int b = blockIdx.z, c = blockIdx.y, n0 = blockIdx.x * 64;
    const float* src = x + ((size_t)(b*C_+c)*N_ + n0) * K_;   // 1024 contiguous floats
    int tid = threadIdx.x;
#pragma unroll
    for (int r = 0; r < 4; r++) { int i = tid + r*256; s[i>>4][i&15] = src[i]; }
    __syncthreads();
    int nn = tid & 63, kb = tid >> 6;
#pragma unroll
    for (int r = 0; r < 4; r++) {
        int kq = kb + r*4;
        g_xt[((size_t)(b*K_+kq)*C_ + c)*N_ + n0 + nn] = s[nn][kq];
    }
}

// ---------------- GEMM microkernel helpers (64x64x16 tile, 4x4/thread) ----------------
#define FMA16(acc, a, bv)                                  \
    acc[0][0]=fmaf(a.x,bv.x,acc[0][0]); acc[0][1]=fmaf(a.x,bv.y,acc[0][1]); \
    acc[0][2]=fmaf(a.x,bv.z,acc[0][2]); acc[0][3]=fmaf(a.x,bv.w,acc[0][3]); \
    acc[1][0]=fmaf(a.y,bv.x,acc[1][0]); acc[1][1]=fmaf(a.y,bv.y,acc[1][1]); \
    acc[1][2]=fmaf(a.y,bv.z,acc[1][2]); acc[1][3]=fmaf(a.y,bv.w,acc[1][3]); \
    acc[2][0]=fmaf(a.z,bv.x,acc[2][0]); acc[2][1]=fmaf(a.z,bv.y,acc[2][1]); \
    acc[2][2]=fmaf(a.z,bv.z,acc[2][2]); acc[2][3]=fmaf(a.z,bv.w,acc[2][3]); \
    acc[3][0]=fmaf(a.w,bv.x,acc[3][0]); acc[3][1]=fmaf(a.w,bv.y,acc[3][1]); \
    acc[3][2]=fmaf(a.w,bv.z,acc[3][2]); acc[3][3]=fmaf(a.w,bv.w,acc[3][3]);

// ---------------- 2: stacked channel GEMM  out[640,1024] = Wall @ xt[bk]  ----------------
__global__ void k_stage2() {
    __shared__ float As[16][64], Bs[16][64];
    int bk = blockIdx.z;
    int m0 = blockIdx.y * 64, n0 = blockIdx.x * 64;
    const float* X = g_xt + (size_t)bk * C_ * N_;
    int tid = threadIdx.x, tx = tid & 15, ty = tid >> 4;
    int t4 = tid * 4;
    int amm = t4 >> 4, akk = t4 & 15;
    int bkk = t4 >> 6, bnn = t4 & 63;
    float acc[4][4] = {};
    for (int kc = 0; kc < C_; kc += 16) {
        float4 av = *(const float4*)&g_wall[(m0+amm)*C_ + kc + akk];
        As[akk  ][amm] = av.x; As[akk+1][amm] = av.y;
        As[akk+2][amm] = av.z; As[akk+3][amm] = av.w;
        *(float4*)&Bs[bkk][bnn] = *(const float4*)&X[(size_t)(kc+bkk)*N_ + n0 + bnn];
        __syncthreads();
#pragma unroll
        for (int kk = 0; kk < 16; kk++) {
            float4 a  = *(const float4*)&As[kk][ty*4];
            float4 bv = *(const float4*)&Bs[kk][tx*4];
            FMA16(acc, a, bv)
        }
        __syncthreads();
    }
#pragma unroll
    for (int i = 0; i < 4; i++) {
        int r = m0 + ty*4 + i;
        float bias = g_ball[r];
        float* dst;
        if      (r < 64)  dst = g_q  + ((size_t)bk*CQ_ + r      ) * N_;
        else if (r < 128) dst = g_k  + ((size_t)bk*CQ_ + (r-64) ) * N_;
        else if (r < 384) dst = g_u  + ((size_t)bk*C_  + (r-128)) * N_;
        else              dst = g_t1 + ((size_t)bk*C_  + (r-384)) * N_;
        float4 v = make_float4(acc[i][0]+bias, acc[i][1]+bias, acc[i][2]+bias, acc[i][3]+bias);
        *(float4*)&dst[n0 + tx*4] = v;
    }
}

// ---------------- 3: energy E[n,m] = sum_d Q[d,n]*K[d,m]  (TN) ----------------
__global__ void k_energy() {
    __shared__ float As[16][64], Bs[16][64];
    int bk = blockIdx.z, n0 = blockIdx.y * 64, m0 = blockIdx.x * 64;
    const float* Q  = g_q + (size_t)bk * CQ_ * N_;
    const float* Kp = g_k + (size_t)bk * CQ_ * N_;
    float* E = g_e + (size_t)bk * N_ * N_;
    int tid = threadIdx.x, tx = tid & 15, ty = tid >> 4;
    int t4 = tid * 4;
    int ldd = t4 >> 6, lnn = t4 & 63;
    float acc[4][4] = {};
    for (int dc = 0; dc < CQ_; dc += 16) {
        *(float4*)&As[ldd][lnn] = *(const float4*)&Q [(size_t)(dc+ldd)*N_ + n0 + lnn];
        *(float4*)&Bs[ldd][lnn] = *(const float4*)&Kp[(size_t)(dc+ldd)*N_ + m0 + lnn];
        __syncthreads();
#pragma unroll
        for (int kk = 0; kk < 16; kk++) {
            float4 a  = *(const float4*)&As[kk][ty*4];
            float4 bv = *(const float4*)&Bs[kk][tx*4];
            FMA16(acc, a, bv)
        }
        __syncthreads();
    }
#pragma unroll
    for (int i = 0; i < 4; i++) {
        float4 v = make_float4(acc[i][0], acc[i][1], acc[i][2], acc[i][3]);
        *(float4*)&E[(size_t)(n0+ty*4+i)*N_ + m0 + tx*4] = v;
    }
}

// ---------------- 4: softmax(m) per (b,k,n) + renorm over k, in place ----------------
__global__ void k_softmax() {
    int b = blockIdx.x >> 10, n = blockIdx.x & 1023;
    int tid = threadIdx.x, lane = tid & 31, wid = tid >> 5;
    __shared__ float wred[8][16];
    __shared__ float gmax[16], ginv[16];
    float vals[16][4];
    // pass 1: load + per-k max
#pragma unroll
    for (int k = 0; k < 16; k++) {
        const float* row = g_e + ((size_t)(b*K_+k)*N_ + n) * N_;
        float m = -1e30f;
#pragma unroll
        for (int j = 0; j < 4; j++) { vals[k][j] = row[tid + j*256]; m = fmaxf(m, vals[k][j]); }
#pragma unroll
        for (int o = 16; o; o >>= 1) m = fmaxf(m, __shfl_xor_sync(0xffffffffu, m, o));
        if (lane == 0) wred[wid][k] = m;
    }
    __syncthreads();
    if (tid < 16) {
        float m = -1e30f;
#pragma unroll
        for (int w = 0; w < 8; w++) m = fmaxf(m, wred[w][tid]);
        gmax[tid] = m;
    }
    __syncthreads();
    // pass 2: exp + per-k sum
#pragma unroll
    for (int k = 0; k < 16; k++) {
        float mk = gmax[k], s = 0.f;
#pragma unroll
        for (int j = 0; j < 4; j++) { vals[k][j] = __expf(vals[k][j] - mk); s += vals[k][j]; }
#pragma unroll
        for (int o = 16; o; o >>= 1) s += __shfl_xor_sync(0xffffffffu, s, o);
        if (lane == 0) wred[wid][k] = s;
    }
    __syncthreads();
    if (tid < 16) {
        float s = 0.f;
#pragma unroll
        for (int w = 0; w < 8; w++) s += wred[w][tid];
        ginv[tid] = 1.f / s;
    }
    __syncthreads();
    // softmax values + k-sum per m, then renormalize and store
    float asum[4] = {0.f, 0.f, 0.f, 0.f};
#pragma unroll
    for (int k = 0; k < 16; k++) {
        float inv = ginv[k];
#pragma unroll
        for (int j = 0; j < 4; j++) { vals[k][j] *= inv; asum[j] += vals[k][j]; }
    }
#pragma unroll
    for (int j = 0; j < 4; j++) asum[j] = 1.f / (1e-9f + asum[j]);
#pragma unroll
    for (int k = 0; k < 16; k++) {
        float* row = g_e + ((size_t)(b*K_+k)*N_ + n) * N_;
#pragma unroll
        for (int j = 0; j < 4; j++) row[tid + j*256] = vals[k][j] * asum[j];
    }
}

// ---------------- 5: t = t1 - U @ attn   (NN, K=1024) ----------------
__global__ void k_xr() {
    __shared__ float As[16][64], Bs[16][64];
    int bk = blockIdx.z, c0 = blockIdx.y * 64, m0 = blockIdx.x * 64;
    const float* U = g_u + (size_t)bk * C_ * N_;
    const float* A = g_e + (size_t)bk * N_ * N_;
    int tid = threadIdx.x, tx = tid & 15, ty = tid >> 4;
    int t4 = tid * 4;
    int acc_cc = t4 >> 4, ann = t4 & 15;
    int bnn = t4 >> 6, bmm = t4 & 63;
    float acc[4][4] = {};
    for (int nc = 0; nc < N_; nc += 16) {
        float4 av = *(const float4*)&U[(size_t)(c0+acc_cc)*N_ + nc + ann];
        As[ann  ][acc_cc] = av.x; As[ann+1][acc_cc] = av.y;
        As[ann+2][acc_cc] = av.z; As[ann+3][acc_cc] = av.w;
        *(float4*)&Bs[bnn][bmm] = *(const float4*)&A[(size_t)(nc+bnn)*N_ + m0 + bmm];
        __syncthreads();
#pragma unroll
        for (int kk = 0; kk < 16; kk++) {
            float4 a  = *(const float4*)&As[kk][ty*4];
            float4 bv = *(const float4*)&Bs[kk][tx*4];
            FMA16(acc, a, bv)
        }
        __syncthreads();
    }
#pragma unroll
    for (int i = 0; i < 4; i++) {
        size_t idx = ((size_t)bk*C_ + c0 + ty*4 + i) * N_ + m0 + tx*4;
        float4 t1v = *(const float4*)&g_t1[idx];
        float4 o = make_float4(t1v.x - acc[i][0], t1v.y - acc[i][1],
                               t1v.z - acc[i][2], t1v.w - acc[i][3]);
        *(float4*)&g_t[idx] = o;
    }
}

// ---------------- 6: BN statistics per channel ----------------
__global__ void k_stats() {
    int c = blockIdx.x, tid = threadIdx.x;
    __shared__ float rs[256], rs2[256];
    float s = 0.f, ss = 0.f;
    for (int bk = 0; bk < BK_; bk++) {
        const float* p = g_t + ((size_t)bk*C_ + c) * N_;
        for (int i = tid; i < N_; i += 256) { float v = p[i]; s += v; ss = fmaf(v, v, ss); }
    }
    rs[tid] = s; rs2[tid] = ss;
    __syncthreads();
    for (int o = 128; o; o >>= 1) {
        if (tid < o) { rs[tid] += rs[tid+o]; rs2[tid] += rs2[tid+o]; }
        __syncthreads();
    }
    if (tid == 0) {
        const float inv = 1.f / (float)(B_*N_*K_);
        float mean = rs[0] * inv;
        float var  = rs2[0] * inv - mean * mean;
        g_mean[c] = mean;
        g_rstd[c] = rsqrtf(var + 1e-5f);
    }
}

// ---------------- 7: out = x + relu(BN(t)) with transpose back to [B,C,N,K] ----------------
__global__ void k_final(const float* __restrict__ x, const float* __restrict__ gamma,
                        const float* __restrict__ beta, float* __restrict__ out) {
    __shared__ float s[16][65];
    int b = blockIdx.z, c = blockIdx.y, n0 = blockIdx.x * 64;
    int tid = threadIdx.x;
    float mean = g_mean[c], rstd = g_rstd[c], ga = gamma[c], be = beta[c];
    int nn = tid & 63, kb = tid >> 6;
#pragma unroll
    for (int r = 0; r < 4; r++) {
        int kq = kb + r*4;
        s[kq][nn] = g_t[((size_t)(b*K_+kq)*C_ + c)*N_ + n0 + nn];
    }
    __syncthreads();
    const float* xs = x   + ((size_t)(b*C_+c)*N_ + n0) * K_;
    float*       os = out + ((size_t)(b*C_+c)*N_ + n0) * K_;
#pragma unroll
    for (int r = 0; r < 4; r++) {
        int i = tid + r*256;
        float tv = s[i & 15][i >> 4];
        float v = fmaf((tv - mean) * rstd, ga, be);
        v = fmaxf(v, 0.f);
        os[i] = xs[i] + v;
    }
}

// ---------------- launch ----------------
extern "C" void kernel_launch(void* const* d_in, const int* in_sizes, int n_in,
                              void* d_out, int out_size) {
    const float* x     = (const float*)d_in[0];
    const float* q_w   = (const float*)d_in[1];
    const float* k_w   = (const float*)d_in[2];
    const float* v_w   = (const float*)d_in[3];
    const float* v_b   = (const float*)d_in[4];
    const float* t_w   = (const float*)d_in[5];
    const float* t_b   = (const float*)d_in[6];
    const float* gamma = (const float*)d_in[7];
    const float* beta  = (const float*)d_in[8];
    float* out = (float*)d_out;

    k_prep   <<<MALL, 256>>>(q_w, k_w, v_w, v_b, t_w, t_b);
    k_xpose  <<<dim3(N_/64, C_, B_), 256>>>(x);
    k_stage2 <<<dim3(N_/64, MALL/64, BK_), 256>>>();
    k_energy <<<dim3(N_/64, N_/64, BK_), 256>>>();
    k_softmax<<<B_*N_, 256>>>();
    k_xr     <<<dim3(N_/64, C_/64, BK_), 256>>>();
    k_stats  <<<C_, 256>>>();
    k_final  <<<dim3(N_/64, C_, B_), 256>>>(x, gamma, beta, out);
}

// round 10
// speedup vs baseline: 1.8621x; 1.8621x over previous
#include <cuda_runtime.h>
#include <cstdint>

#define B_ 8
#define C_ 256
#define N_ 1024
#define K_ 16
#define CQ_ 64
#define BK_ (B_*K_)
#define MALL 640
#define NELEM_T ((size_t)BK_*C_*N_)

// ---------------- scratch ----------------
__device__ float g_wall[MALL*C_];
__device__ float g_ball[MALL];
__device__ float g_xt[(size_t)BK_*N_*C_];   // x transposed [B,K,N,C] (c contiguous)
__device__ float g_q[(size_t)BK_*CQ_*N_];
__device__ float g_k[(size_t)BK_*CQ_*N_];
__device__ float g_u[NELEM_T];              // [bk][c][n]
__device__ float g_t1[NELEM_T];
__device__ float g_t[NELEM_T];
__device__ float g_e[(size_t)BK_*N_*N_];    // energy/attn [bk][n][m]
__device__ float g_mean[C_], g_rstd[C_];

__device__ __forceinline__ float tf32r(float x) {
    float r; asm("cvt.rna.tf32.f32 %0, %1;" : "=f"(r) : "f"(x)); return r;
}
__device__ __forceinline__ void cvt4(float4& v) {
    v.x = tf32r(v.x); v.y = tf32r(v.y); v.z = tf32r(v.z); v.w = tf32r(v.w);
}

// ---------------- 0: fold weights ----------------
__global__ void k_prep(const float* __restrict__ qw, const float* __restrict__ kw,
                       const float* __restrict__ vw, const float* __restrict__ vb,
                       const float* __restrict__ tw, const float* __restrict__ tb) {
    int r = blockIdx.x, c = threadIdx.x;
    if (r < 64) { g_wall[r*C_+c] = qw[r*C_+c]; if (c==0) g_ball[r] = 0.f; }
    else if (r < 128) { g_wall[r*C_+c] = kw[(r-64)*C_+c]; if (c==0) g_ball[r] = 0.f; }
    else if (r < 384) {
        int o = r - 128; float s = 0.f;
        for (int c2 = 0; c2 < C_; c2++) s = fmaf(tw[o*C_+c2], vw[c2*C_+c], s);
        g_wall[r*C_+c] = s;
        if (c == 0) {
            float sb = 0.f;
            for (int c2 = 0; c2 < C_; c2++) sb = fmaf(tw[o*C_+c2], vb[c2], sb);
            g_ball[r] = sb;
        }
    } else { int o = r - 384; g_wall[r*C_+c] = tw[o*C_+c]; if (c==0) g_ball[r] = tb[o]; }
}

// ---------------- 1: x [B,C,N,K] -> xt [B,K,N,C] ----------------
__global__ void k_xpose(const float* __restrict__ x) {
    __shared__ float s[32][132];
    int b = blockIdx.z, c0 = blockIdx.y * 32, n0 = blockIdx.x * 8;
    int tid = threadIdx.x;
    {
        int cl = tid >> 3, f = tid & 7;
        const float* src = x + ((size_t)(b*C_ + c0 + cl)*N_ + n0) * K_;
#pragma unroll
        for (int i = 0; i < 4; i++) {
            int j = (f + i*8) * 4;
            *(float4*)&s[cl][j] = *(const float4*)(src + j);
        }
    }
    __syncthreads();
    int q2 = tid >> 1, h = tid & 1;
    int nl = q2 & 7, kk = q2 >> 3;
    int p = nl*16 + kk;
    float* dst = g_xt + ((size_t)((b*K_+kk)*N_) + n0 + nl)*C_ + c0 + h*16;
#pragma unroll
    for (int q = 0; q < 4; q++) {
        int cc = h*16 + q*4;
        *(float4*)(dst + q*4) = make_float4(s[cc][p], s[cc+1][p], s[cc+2][p], s[cc+3][p]);
    }
}

#define FMA16(acc, a, bv)                                  \
    acc[0][0]=fmaf(a.x,bv.x,acc[0][0]); acc[0][1]=fmaf(a.x,bv.y,acc[0][1]); \
    acc[0][2]=fmaf(a.x,bv.z,acc[0][2]); acc[0][3]=fmaf(a.x,bv.w,acc[0][3]); \
    acc[1][0]=fmaf(a.y,bv.x,acc[1][0]); acc[1][1]=fmaf(a.y,bv.y,acc[1][1]); \
    acc[1][2]=fmaf(a.y,bv.z,acc[1][2]); acc[1][3]=fmaf(a.y,bv.w,acc[1][3]); \
    acc[2][0]=fmaf(a.z,bv.x,acc[2][0]); acc[2][1]=fmaf(a.z,bv.y,acc[2][1]); \
    acc[2][2]=fmaf(a.z,bv.z,acc[2][2]); acc[2][3]=fmaf(a.z,bv.w,acc[2][3]); \
    acc[3][0]=fmaf(a.w,bv.x,acc[3][0]); acc[3][1]=fmaf(a.w,bv.y,acc[3][1]); \
    acc[3][2]=fmaf(a.w,bv.z,acc[3][2]); acc[3][3]=fmaf(a.w,bv.w,acc[3][3]);

// ---------------- 2a: q,k GEMM (fp32 SIMT, Wall rows 0..127) ----------------
__global__ void k_stage2qk() {
    __shared__ float As[16][68], Bs[16][68];
    int bk = blockIdx.z;
    int m0 = blockIdx.y * 64, n0 = blockIdx.x * 64;
    const float* X = g_xt + (size_t)bk * N_ * C_;
    int tid = threadIdx.x, tx = tid & 15, ty = tid >> 4;
    int amm = tid >> 2, acg = (tid & 3) * 4;
    float acc[4][4] = {};
    for (int kc = 0; kc < C_; kc += 16) {
        float4 av = *(const float4*)&g_wall[(m0+amm)*C_ + kc + acg];
        As[acg][amm]=av.x; As[acg+1][amm]=av.y; As[acg+2][amm]=av.z; As[acg+3][amm]=av.w;
        float4 bv = *(const float4*)&X[(size_t)(n0+amm)*C_ + kc + acg];
        Bs[acg][amm]=bv.x; Bs[acg+1][amm]=bv.y; Bs[acg+2][amm]=bv.z; Bs[acg+3][amm]=bv.w;
        __syncthreads();
#pragma unroll
        for (int kk = 0; kk < 16; kk++) {
            float4 a  = *(const float4*)&As[kk][ty*4];
            float4 b2 = *(const float4*)&Bs[kk][tx*4];
            FMA16(acc, a, b2)
        }
        __syncthreads();
    }
#pragma unroll
    for (int i = 0; i < 4; i++) {
        int r = m0 + ty*4 + i;
        float* dst = (r < 64) ? (g_q + ((size_t)bk*CQ_ + r)*N_)
                              : (g_k + ((size_t)bk*CQ_ + (r-64))*N_);
        *(float4*)&dst[n0 + tx*4] = make_float4(acc[i][0], acc[i][1], acc[i][2], acc[i][3]);
    }
}

// ---------------- mma.sync tf32 GEMM: MODE 0 = u/t1 conv, MODE 1 = xr ----------------
// CTA tile 128x128, 8 warps (4m x 2n), warp tile 32x64, k-chunk 32, double buffer.
#define SAPITCH 36
#define SABUF (128*SAPITCH)          // 4608 floats
#define SMEM_MMA (4*SABUF*4)         // 73728 bytes

template<int MODE>
__global__ void __launch_bounds__(256) k_mma() {
    extern __shared__ float smf[];
    float* sa = smf;                 // [2][128*36]  A: [m][k]
    float* sb = smf + 2*SABUF;       // MODE0 [2][n][k] pitch36; MODE1 [2][k][m] pitch132
    int tid = threadIdx.x, lane = tid & 31, wid = tid >> 5;
    int bk = blockIdx.z;
    int blk_m, blk_n, NCH, lda;
    const float *Ap, *Bp;
    if (MODE == 0) {
        blk_m = blockIdx.x & 3; blk_n = blockIdx.x >> 2; NCH = C_/32;
        Ap = g_wall + (size_t)(128 + blk_m*128) * C_;                lda = C_;
        Bp = g_xt + (size_t)bk*N_*C_ + (size_t)(blk_n*128)*C_;       // [n][c]
    } else {
        blk_m = blockIdx.x & 1; blk_n = blockIdx.x >> 1; NCH = N_/32;
        Ap = g_u + ((size_t)bk*C_ + blk_m*128)*N_;                   lda = N_;
        Bp = g_e + (size_t)bk*N_*N_;                                 // [n][m]
    }
    int m0col = blk_n * 128;
    float4 ra[4], rb[4];

    auto loadG = [&](int kc) {
#pragma unroll
        for (int i = 0; i < 4; i++) {
            int f = tid + i*256, row = f >> 3, cg = f & 7;
            ra[i] = *(const float4*)(Ap + (size_t)row*lda + kc + cg*4);
            cvt4(ra[i]);
        }
        if (MODE == 0) {
#pragma unroll
            for (int i = 0; i < 4; i++) {
                int f = tid + i*256, row = f >> 3, cg = f & 7;
                rb[i] = *(const float4*)(Bp + (size_t)row*C_ + kc + cg*4);
                cvt4(rb[i]);
            }
        } else {
#pragma unroll
            for (int i = 0; i < 4; i++) {
                int f = tid + i*256, nr = f >> 5, mg = f & 31;
                rb[i] = *(const float4*)(Bp + (size_t)(kc+nr)*N_ + m0col + mg*4);
                cvt4(rb[i]);
            }
        }
    };
    auto storeS = [&](int buf) {
#pragma unroll
        for (int i = 0; i < 4; i++) {
            int f = tid + i*256, row = f >> 3, cg = f & 7;
            *(float4*)&sa[buf*SABUF + row*SAPITCH + cg*4] = ra[i];
        }
        if (MODE == 0) {
#pragma unroll
            for (int i = 0; i < 4; i++) {
                int f = tid + i*256, row = f >> 3, cg = f & 7;
                *(float4*)&sb[buf*SABUF + row*SAPITCH + cg*4] = rb[i];
            }
        } else {
#pragma unroll
            for (int i = 0; i < 4; i++) {
                int f = tid + i*256, nr = f >> 5, mg = f & 31;
                *(float4*)&sb[buf*SABUF + nr*132 + mg*4] = rb[i];
            }
        }
    };

    int wm = (wid & 3) * 32, wn = (wid >> 2) * 64;
    float acc[2][8][4] = {};

    loadG(0); storeS(0); __syncthreads();
    for (int c = 0; c < NCH; c++) {
        if (c + 1 < NCH) loadG((c+1)*32);
        const float* A  = sa + (c & 1)*SABUF;
        const float* Bz = sb + (c & 1)*SABUF;
#pragma unroll
        for (int ks = 0; ks < 4; ks++) {
            int k0 = ks*8 + (lane & 3);
            uint32_t af[2][4];
#pragma unroll
            for (int i = 0; i < 2; i++) {
                int m = wm + i*16 + (lane >> 2);
                af[i][0] = __float_as_uint(A[m*SAPITCH + k0]);
                af[i][1] = __float_as_uint(A[(m+8)*SAPITCH + k0]);
                af[i][2] = __float_as_uint(A[m*SAPITCH + k0 + 4]);
                af[i][3] = __float_as_uint(A[(m+8)*SAPITCH + k0 + 4]);
            }
#pragma unroll
            for (int j = 0; j < 8; j++) {
                int nc = wn + j*8 + (lane >> 2);
                uint32_t b0, b1;
                if (MODE == 0) {
                    b0 = __float_as_uint(Bz[nc*SAPITCH + k0]);
                    b1 = __float_as_uint(Bz[nc*SAPITCH + k0 + 4]);
                } else {
                    b0 = __float_as_uint(Bz[k0*132 + nc]);
                    b1 = __float_as_uint(Bz[(k0+4)*132 + nc]);
                }
#pragma unroll
                for (int i = 0; i < 2; i++)
                    asm volatile(
                        "mma.sync.aligned.m16n8k8.row.col.f32.tf32.tf32.f32 "
                        "{%0,%1,%2,%3}, {%4,%5,%6,%7}, {%8,%9}, {%0,%1,%2,%3};"
                        : "+f"(acc[i][j][0]), "+f"(acc[i][j][1]),
                          "+f"(acc[i][j][2]), "+f"(acc[i][j][3])
                        : "r"(af[i][0]), "r"(af[i][1]), "r"(af[i][2]), "r"(af[i][3]),
                          "r"(b0), "r"(b1));
            }
        }
        if (c + 1 < NCH) { __syncthreads(); storeS((c+1) & 1); __syncthreads(); }
    }

    // ---- epilogue ----
    if (MODE == 0) {
        int arow0 = 128 + blk_m*128;
        float* dstb = (arow0 < 384) ? g_u  + ((size_t)bk*C_ + (arow0-128))*N_
                                    : g_t1 + ((size_t)bk*C_ + (arow0-384))*N_;
#pragma unroll
        for (int i = 0; i < 2; i++) {
            int r0 = wm + i*16 + (lane >> 2);
            float bv0 = g_ball[arow0 + r0], bv1 = g_ball[arow0 + r0 + 8];
#pragma unroll
            for (int j = 0; j < 8; j++) {
                int col = m0col + wn + j*8 + 2*(lane & 3);
                *(float2*)&dstb[(size_t)r0*N_ + col] =
                    make_float2(acc[i][j][0] + bv0, acc[i][j][1] + bv0);
                *(float2*)&dstb[(size_t)(r0+8)*N_ + col] =
                    make_float2(acc[i][j][2] + bv1, acc[i][j][3] + bv1);
            }
        }
    } else {
#pragma unroll
        for (int i = 0; i < 2; i++) {
            int r0 = blk_m*128 + wm + i*16 + (lane >> 2);
#pragma unroll
            for (int j = 0; j < 8; j++) {
                int col = m0col + wn + j*8 + 2*(lane & 3);
                size_t i0 = ((size_t)bk*C_ + r0)*N_ + col;
                size_t i1 = i0 + (size_t)8*N_;
                float2 ta = *(const float2*)&g_t1[i0];
                float2 tb = *(const float2*)&g_t1[i1];
                *(float2*)&g_t[i0] = make_float2(ta.x - acc[i][j][0], ta.y - acc[i][j][1]);
                *(float2*)&g_t[i1] = make_float2(tb.x - acc[i][j][2], tb.y - acc[i][j][3]);
            }
        }
    }
}

// ---------------- 3: energy (fp32 SIMT) ----------------
__global__ void k_energy() {
    __shared__ float As[16][64], Bs[16][64];
    int bk = blockIdx.z, n0 = blockIdx.y * 64, m0 = blockIdx.x * 64;
    const float* Q  = g_q + (size_t)bk * CQ_ * N_;
    const float* Kp = g_k + (size_t)bk * CQ_ * N_;
    float* E = g_e + (size_t)bk * N_ * N_;
    int tid = threadIdx.x, tx = tid & 15, ty = tid >> 4;
    int t4 = tid * 4, ldd = t4 >> 6, lnn = t4 & 63;
    float acc[4][4] = {};
    for (int dc = 0; dc < CQ_; dc += 16) {
        *(float4*)&As[ldd][lnn] = *(const float4*)&Q [(size_t)(dc+ldd)*N_ + n0 + lnn];
        *(float4*)&Bs[ldd][lnn] = *(const float4*)&Kp[(size_t)(dc+ldd)*N_ + m0 + lnn];
        __syncthreads();
#pragma unroll
        for (int kk = 0; kk < 16; kk++) {
            float4 a  = *(const float4*)&As[kk][ty*4];
            float4 bv = *(const float4*)&Bs[kk][tx*4];
            FMA16(acc, a, bv)
        }
        __syncthreads();
    }
#pragma unroll
    for (int i = 0; i < 4; i++)
        *(float4*)&E[(size_t)(n0+ty*4+i)*N_ + m0 + tx*4] =
            make_float4(acc[i][0], acc[i][1], acc[i][2], acc[i][3]);
}

// ---------------- 4: softmax + k-renorm in place ----------------
__global__ void k_softmax() {
    int b = blockIdx.x >> 10, n = blockIdx.x & 1023;
    int tid = threadIdx.x, lane = tid & 31, wid = tid >> 5;
    __shared__ float wred[8][16], gmax[16], ginv[16];
    float vals[16][4];
#pragma unroll
    for (int k = 0; k < 16; k++) {
        const float* row = g_e + ((size_t)(b*K_+k)*N_ + n) * N_;
        float m = -1e30f;
#pragma unroll
        for (int j = 0; j < 4; j++) { vals[k][j] = row[tid + j*256]; m = fmaxf(m, vals[k][j]); }
#pragma unroll
        for (int o = 16; o; o >>= 1) m = fmaxf(m, __shfl_xor_sync(0xffffffffu, m, o));
        if (lane == 0) wred[wid][k] = m;
    }
    __syncthreads();
    if (tid < 16) {
        float m = -1e30f;
#pragma unroll
        for (int w = 0; w < 8; w++) m = fmaxf(m, wred[w][tid]);
        gmax[tid] = m;
    }
    __syncthreads();
#pragma unroll
    for (int k = 0; k < 16; k++) {
        float mk = gmax[k], s = 0.f;
#pragma unroll
        for (int j = 0; j < 4; j++) { vals[k][j] = __expf(vals[k][j] - mk); s += vals[k][j]; }
#pragma unroll
        for (int o = 16; o; o >>= 1) s += __shfl_xor_sync(0xffffffffu, s, o);
        if (lane == 0) wred[wid][k] = s;
    }
    __syncthreads();
    if (tid < 16) {
        float s = 0.f;
#pragma unroll
        for (int w = 0; w < 8; w++) s += wred[w][tid];
        ginv[tid] = 1.f / s;
    }
    __syncthreads();
    float asum[4] = {0.f, 0.f, 0.f, 0.f};
#pragma unroll
    for (int k = 0; k < 16; k++) {
        float inv = ginv[k];
#pragma unroll
        for (int j = 0; j < 4; j++) { vals[k][j] *= inv; asum[j] += vals[k][j]; }
    }
#pragma unroll
    for (int j = 0; j < 4; j++) asum[j] = 1.f / (1e-9f + asum[j]);
#pragma unroll
    for (int k = 0; k < 16; k++) {
        float* row = g_e + ((size_t)(b*K_+k)*N_ + n) * N_;
#pragma unroll
        for (int j = 0; j < 4; j++) row[tid + j*256] = vals[k][j] * asum[j];
    }
}

// ---------------- 6: BN stats ----------------
__global__ void k_stats() {
    int c = blockIdx.x, tid = threadIdx.x;
    __shared__ float rs[256], rs2[256];
    float s = 0.f, ss = 0.f;
    for (int bk = 0; bk < BK_; bk++) {
        const float* p = g_t + ((size_t)bk*C_ + c) * N_;
        for (int i = tid; i < N_; i += 256) { float v = p[i]; s += v; ss = fmaf(v, v, ss); }
    }
    rs[tid] = s; rs2[tid] = ss;
    __syncthreads();
    for (int o = 128; o; o >>= 1) {
        if (tid < o) { rs[tid] += rs[tid+o]; rs2[tid] += rs2[tid+o]; }
        __syncthreads();
    }
    if (tid == 0) {
        const float inv = 1.f / (float)(B_*N_*K_);
        float mean = rs[0] * inv;
        g_mean[c] = mean;
        g_rstd[c] = rsqrtf(rs2[0]*inv - mean*mean + 1e-5f);
    }
}

// ---------------- 7: out = x + relu(BN(t)), back to [B,C,N,K] ----------------
__global__ void k_final(const float* __restrict__ x, const float* __restrict__ gamma,
                        const float* __restrict__ beta, float* __restrict__ out) {
    __shared__ float s[16][65];
    int b = blockIdx.z, c = blockIdx.y, n0 = blockIdx.x * 64;
    int tid = threadIdx.x;
    float mean = g_mean[c], rstd = g_rstd[c], ga = gamma[c], be = beta[c];
    int nn = tid & 63, kb = tid >> 6;
#pragma unroll
    for (int r = 0; r < 4; r++) {
        int kq = kb + r*4;
        s[kq][nn] = g_t[((size_t)(b*K_+kq)*C_ + c)*N_ + n0 + nn];
    }
    __syncthreads();
    const float* xs = x   + ((size_t)(b*C_+c)*N_ + n0) * K_;
    float*       os = out + ((size_t)(b*C_+c)*N_ + n0) * K_;
#pragma unroll
    for (int r = 0; r < 4; r++) {
        int i = tid + r*256;
        float v = fmaf((s[i & 15][i >> 4] - mean) * rstd, ga, be);
        os[i] = xs[i] + fmaxf(v, 0.f);
    }
}

// ---------------- launch ----------------
extern "C" void kernel_launch(void* const* d_in, const int* in_sizes, int n_in,
                              void* d_out, int out_size) {
    const float* x     = (const float*)d_in[0];
    const float* q_w   = (const float*)d_in[1];
    const float* k_w   = (const float*)d_in[2];
    const float* v_w   = (const float*)d_in[3];
    const float* v_b   = (const float*)d_in[4];
    const float* t_w   = (const float*)d_in[5];
    const float* t_b   = (const float*)d_in[6];
    const float* gamma = (const float*)d_in[7];
    const float* beta  = (const float*)d_in[8];
    float* out = (float*)d_out;

    cudaFuncSetAttribute(k_mma<0>, cudaFuncAttributeMaxDynamicSharedMemorySize, SMEM_MMA);
    cudaFuncSetAttribute(k_mma<1>, cudaFuncAttributeMaxDynamicSharedMemorySize, SMEM_MMA);

    k_prep    <<<MALL, 256>>>(q_w, k_w, v_w, v_b, t_w, t_b);
    k_xpose   <<<dim3(N_/8, C_/32, B_), 256>>>(x);
    k_stage2qk<<<dim3(N_/64, 2, BK_), 256>>>();
    k_mma<0>  <<<dim3(32, 1, BK_), 256, SMEM_MMA>>>();
    k_energy  <<<dim3(N_/64, N_/64, BK_), 256>>>();
    k_softmax <<<B_*N_, 256>>>();
    k_mma<1>  <<<dim3(16, 1, BK_), 256, SMEM_MMA>>>();
    k_stats   <<<C_, 256>>>();
    k_final   <<<dim3(N_/64, C_, B_), 256>>>(x, gamma, beta, out);
}

// round 14
// speedup vs baseline: 2.1299x; 1.1438x over previous
#include <cuda_runtime.h>
#include <cstdint>

#define B_ 8
#define C_ 256
#define N_ 1024
#define K_ 16
#define CQ_ 64
#define BK_ (B_*K_)
#define MALL 640
#define NELEM_T ((size_t)BK_*C_*N_)

// ---------------- scratch ----------------
__device__ float g_wall[MALL*C_];
__device__ float g_ball[MALL];
__device__ float g_xt[(size_t)BK_*N_*C_];   // x transposed [B,K,N,C]
__device__ float g_qt[(size_t)BK_*N_*CQ_];  // Q transposed [bk][n][cq]
__device__ float g_k[(size_t)BK_*CQ_*N_];   // [bk][cq][n]
__device__ float g_u[NELEM_T];              // [bk][c][n]
__device__ float g_t1[NELEM_T];
__device__ float g_t[NELEM_T];
__device__ float g_e[(size_t)BK_*N_*N_];    // energy/attn [bk][n][m]
__device__ float g_ps[256*1024], g_pq[256*1024];  // BN partial sums [c][slice]
__device__ float g_mean[C_], g_rstd[C_];

__device__ __forceinline__ float tf32r(float x) {
    float r; asm("cvt.rna.tf32.f32 %0, %1;" : "=f"(r) : "f"(x)); return r;
}
__device__ __forceinline__ void cvt4(float4& v) {
    v.x = tf32r(v.x); v.y = tf32r(v.y); v.z = tf32r(v.z); v.w = tf32r(v.w);
}

// ---------------- 0: fold weights ----------------
__global__ void k_prep(const float* __restrict__ qw, const float* __restrict__ kw,
                       const float* __restrict__ vw, const float* __restrict__ vb,
                       const float* __restrict__ tw, const float* __restrict__ tb) {
    int r = blockIdx.x, c = threadIdx.x;
    if (r < 64) { g_wall[r*C_+c] = qw[r*C_+c]; if (c==0) g_ball[r] = 0.f; }
    else if (r < 128) { g_wall[r*C_+c] = kw[(r-64)*C_+c]; if (c==0) g_ball[r] = 0.f; }
    else if (r < 384) {
        int o = r - 128; float s = 0.f;
        for (int c2 = 0; c2 < C_; c2++) s = fmaf(tw[o*C_+c2], vw[c2*C_+c], s);
        g_wall[r*C_+c] = s;
        if (c == 0) {
            float sb = 0.f;
            for (int c2 = 0; c2 < C_; c2++) sb = fmaf(tw[o*C_+c2], vb[c2], sb);
            g_ball[r] = sb;
        }
    } else { int o = r - 384; g_wall[r*C_+c] = tw[o*C_+c]; if (c==0) g_ball[r] = tb[o]; }
}

// ---------------- 1: x [B,C,N,K] -> xt [B,K,N,C] ----------------
__global__ void k_xpose(const float* __restrict__ x) {
    __shared__ float s[32][132];
    int b = blockIdx.z, c0 = blockIdx.y * 32, n0 = blockIdx.x * 8;
    int tid = threadIdx.x;
    {
        int cl = tid >> 3, f = tid & 7;
        const float* src = x + ((size_t)(b*C_ + c0 + cl)*N_ + n0) * K_;
#pragma unroll
        for (int i = 0; i < 4; i++) {
            int j = (f + i*8) * 4;
            *(float4*)&s[cl][j] = *(const float4*)(src + j);
        }
    }
    __syncthreads();
    int q2 = tid >> 1, h = tid & 1;
    int nl = q2 & 7, kk = q2 >> 3;
    int p = nl*16 + kk;
    float* dst = g_xt + ((size_t)((b*K_+kk)*N_) + n0 + nl)*C_ + c0 + h*16;
#pragma unroll
    for (int q = 0; q < 4; q++) {
        int cc = h*16 + q*4;
        *(float4*)(dst + q*4) = make_float4(s[cc][p], s[cc+1][p], s[cc+2][p], s[cc+3][p]);
    }
}

#define FMA16(acc, a, bv)                                  \
    acc[0][0]=fmaf(a.x,bv.x,acc[0][0]); acc[0][1]=fmaf(a.x,bv.y,acc[0][1]); \
    acc[0][2]=fmaf(a.x,bv.z,acc[0][2]); acc[0][3]=fmaf(a.x,bv.w,acc[0][3]); \
    acc[1][0]=fmaf(a.y,bv.x,acc[1][0]); acc[1][1]=fmaf(a.y,bv.y,acc[1][1]); \
    acc[1][2]=fmaf(a.y,bv.z,acc[1][2]); acc[1][3]=fmaf(a.y,bv.w,acc[1][3]); \
    acc[2][0]=fmaf(a.z,bv.x,acc[2][0]); acc[2][1]=fmaf(a.z,bv.y,acc[2][1]); \
    acc[2][2]=fmaf(a.z,bv.z,acc[2][2]); acc[2][3]=fmaf(a.z,bv.w,acc[2][3]); \
    acc[3][0]=fmaf(a.w,bv.x,acc[3][0]); acc[3][1]=fmaf(a.w,bv.y,acc[3][1]); \
    acc[3][2]=fmaf(a.w,bv.z,acc[3][2]); acc[3][3]=fmaf(a.w,bv.w,acc[3][3]);

// ---------------- 2a: q,k GEMM (fp32 SIMT). q written transposed [n][cq]. ----------------
__global__ void k_stage2qk() {
    __shared__ float As[16][68], Bs[16][68];
    __shared__ float st[64][68];   // pitch 68: 16B-aligned rows for float4 access
    int bk = blockIdx.z;
    int m0 = blockIdx.y * 64, n0 = blockIdx.x * 64;
    const float* X = g_xt + (size_t)bk * N_ * C_;
    int tid = threadIdx.x, tx = tid & 15, ty = tid >> 4;
    int amm = tid >> 2, acg = (tid & 3) * 4;
    float acc[4][4] = {};
    for (int kc = 0; kc < C_; kc += 16) {
        float4 av = *(const float4*)&g_wall[(m0+amm)*C_ + kc + acg];
        As[acg][amm]=av.x; As[acg+1][amm]=av.y; As[acg+2][amm]=av.z; As[acg+3][amm]=av.w;
        float4 bv = *(const float4*)&X[(size_t)(n0+amm)*C_ + kc + acg];
        Bs[acg][amm]=bv.x; Bs[acg+1][amm]=bv.y; Bs[acg+2][amm]=bv.z; Bs[acg+3][amm]=bv.w;
        __syncthreads();
#pragma unroll
        for (int kk = 0; kk < 16; kk++) {
            float4 a  = *(const float4*)&As[kk][ty*4];
            float4 b2 = *(const float4*)&Bs[kk][tx*4];
            FMA16(acc, a, b2)
        }
        __syncthreads();
    }
    if (m0 == 0) {
        // q rows: stage transposed tile [n][cq] then write coalesced
#pragma unroll
        for (int i = 0; i < 4; i++)
#pragma unroll
            for (int j = 0; j < 4; j++)
                st[tx*4+j][ty*4+i] = acc[i][j];
        __syncthreads();
        int nn = tid >> 2;
        float* dst = g_qt + ((size_t)bk*N_ + n0 + nn) * CQ_;
#pragma unroll
        for (int q = 0; q < 4; q++) {
            int f = (tid & 3) + q*4;
            *(float4*)(dst + f*4) = *(const float4*)&st[nn][f*4];
        }
    } else {
#pragma unroll
        for (int i = 0; i < 4; i++) {
            int r = m0 + ty*4 + i;
            float* dst = g_k + ((size_t)bk*CQ_ + (r-64))*N_;
            *(float4*)&dst[n0 + tx*4] = make_float4(acc[i][0], acc[i][1], acc[i][2], acc[i][3]);
        }
    }
}

// ---------------- mma.sync tf32 GEMM: MODE 0 = u/t1 conv, MODE 1 = xr (+BN partials) ----------------
#define SAPITCH 36
#define SABUF (128*SAPITCH)
#define SMEM_MMA (4*SABUF*4)

template<int MODE>
__global__ void __launch_bounds__(256) k_mma() {
    extern __shared__ float smf[];
    float* sa = smf;
    float* sb = smf + 2*SABUF;
    __shared__ float s_s[2][128], s_q[2][128];
    int tid = threadIdx.x, lane = tid & 31, wid = tid >> 5;
    int bk = blockIdx.z;
    int blk_m, blk_n, NCH, lda;
    const float *Ap, *Bp;
    if (MODE == 0) {
        blk_m = blockIdx.x & 3; blk_n = blockIdx.x >> 2; NCH = C_/32;
        Ap = g_wall + (size_t)(128 + blk_m*128) * C_;                lda = C_;
        Bp = g_xt + (size_t)bk*N_*C_ + (size_t)(blk_n*128)*C_;
    } else {
        blk_m = blockIdx.x & 1; blk_n = blockIdx.x >> 1; NCH = N_/32;
        Ap = g_u + ((size_t)bk*C_ + blk_m*128)*N_;                   lda = N_;
        Bp = g_e + (size_t)bk*N_*N_;
    }
    int m0col = blk_n * 128;
    float4 ra[4], rb[4];

    auto loadG = [&](int kc) {
#pragma unroll
        for (int i = 0; i < 4; i++) {
            int f = tid + i*256, row = f >> 3, cg = f & 7;
            ra[i] = *(const float4*)(Ap + (size_t)row*lda + kc + cg*4);
            cvt4(ra[i]);
        }
        if (MODE == 0) {
#pragma unroll
            for (int i = 0; i < 4; i++) {
                int f = tid + i*256, row = f >> 3, cg = f & 7;
                rb[i] = *(const float4*)(Bp + (size_t)row*C_ + kc + cg*4);
                cvt4(rb[i]);
            }
        } else {
#pragma unroll
            for (int i = 0; i < 4; i++) {
                int f = tid + i*256, nr = f >> 5, mg = f & 31;
                rb[i] = *(const float4*)(Bp + (size_t)(kc+nr)*N_ + m0col + mg*4);
                cvt4(rb[i]);
            }
        }
    };
    auto storeS = [&](int buf) {
#pragma unroll
        for (int i = 0; i < 4; i++) {
            int f = tid + i*256, row = f >> 3, cg = f & 7;
            *(float4*)&sa[buf*SABUF + row*SAPITCH + cg*4] = ra[i];
        }
        if (MODE == 0) {
#pragma unroll
            for (int i = 0; i < 4; i++) {
                int f = tid + i*256, row = f >> 3, cg = f & 7;
                *(float4*)&sb[buf*SABUF + row*SAPITCH + cg*4] = rb[i];
            }
        } else {
#pragma unroll
            for (int i = 0; i < 4; i++) {
                int f = tid + i*256, nr = f >> 5, mg = f & 31;
                *(float4*)&sb[buf*SABUF + nr*132 + mg*4] = rb[i];
            }
        }
    };

    int wm = (wid & 3) * 32, wn = (wid >> 2) * 64;
    float acc[2][8][4] = {};

    loadG(0); storeS(0); __syncthreads();
    for (int c = 0; c < NCH; c++) {
        if (c + 1 < NCH) loadG((c+1)*32);
        const float* A  = sa + (c & 1)*SABUF;
        const float* Bz = sb + (c & 1)*SABUF;
#pragma unroll
        for (int ks = 0; ks < 4; ks++) {
            int k0 = ks*8 + (lane & 3);
            uint32_t af[2][4];
#pragma unroll
            for (int i = 0; i < 2; i++) {
                int m = wm + i*16 + (lane >> 2);
                af[i][0] = __float_as_uint(A[m*SAPITCH + k0]);
                af[i][1] = __float_as_uint(A[(m+8)*SAPITCH + k0]);
                af[i][2] = __float_as_uint(A[m*SAPITCH + k0 + 4]);
                af[i][3] = __float_as_uint(A[(m+8)*SAPITCH + k0 + 4]);
            }
#pragma unroll
            for (int j = 0; j < 8; j++) {
                int nc = wn + j*8 + (lane >> 2);
                uint32_t b0, b1;
                if (MODE == 0) {
                    b0 = __float_as_uint(Bz[nc*SAPITCH + k0]);
                    b1 = __float_as_uint(Bz[nc*SAPITCH + k0 + 4]);
                } else {
                    b0 = __float_as_uint(Bz[k0*132 + nc]);
                    b1 = __float_as_uint(Bz[(k0+4)*132 + nc]);
                }
#pragma unroll
                for (int i = 0; i < 2; i++)
                    asm volatile(
                        "mma.sync.aligned.m16n8k8.row.col.f32.tf32.tf32.f32 "
                        "{%0,%1,%2,%3}, {%4,%5,%6,%7}, {%8,%9}, {%0,%1,%2,%3};"
                        : "+f"(acc[i][j][0]), "+f"(acc[i][j][1]),
                          "+f"(acc[i][j][2]), "+f"(acc[i][j][3])
                        : "r"(af[i][0]), "r"(af[i][1]), "r"(af[i][2]), "r"(af[i][3]),
                          "r"(b0), "r"(b1));
            }
        }
        if (c + 1 < NCH) { __syncthreads(); storeS((c+1) & 1); __syncthreads(); }
    }

    // ---- epilogue ----
    if (MODE == 0) {
        int arow0 = 128 + blk_m*128;
        float* dstb = (arow0 < 384) ? g_u  + ((size_t)bk*C_ + (arow0-128))*N_
                                    : g_t1 + ((size_t)bk*C_ + (arow0-384))*N_;
#pragma unroll
        for (int i = 0; i < 2; i++) {
            int r0 = wm + i*16 + (lane >> 2);
            float bv0 = g_ball[arow0 + r0], bv1 = g_ball[arow0 + r0 + 8];
#pragma unroll
            for (int j = 0; j < 8; j++) {
                int col = m0col + wn + j*8 + 2*(lane & 3);
                *(float2*)&dstb[(size_t)r0*N_ + col] =
                    make_float2(acc[i][j][0] + bv0, acc[i][j][1] + bv0);
                *(float2*)&dstb[(size_t)(r0+8)*N_ + col] =
                    make_float2(acc[i][j][2] + bv1, acc[i][j][3] + bv1);
            }
        }
    } else {
        float ls[4] = {0,0,0,0}, lq[4] = {0,0,0,0};
#pragma unroll
        for (int i = 0; i < 2; i++) {
            int r0 = blk_m*128 + wm + i*16 + (lane >> 2);
#pragma unroll
            for (int j = 0; j < 8; j++) {
                int col = m0col + wn + j*8 + 2*(lane & 3);
                size_t i0 = ((size_t)bk*C_ + r0)*N_ + col;
                size_t i1 = i0 + (size_t)8*N_;
                float2 ta = *(const float2*)&g_t1[i0];
                float2 tb = *(const float2*)&g_t1[i1];
                float2 o0 = make_float2(ta.x - acc[i][j][0], ta.y - acc[i][j][1]);
                float2 o1 = make_float2(tb.x - acc[i][j][2], tb.y - acc[i][j][3]);
                *(float2*)&g_t[i0] = o0;
                *(float2*)&g_t[i1] = o1;
                ls[i*2]   += o0.x + o0.y; lq[i*2]   += o0.x*o0.x + o0.y*o0.y;
                ls[i*2+1] += o1.x + o1.y; lq[i*2+1] += o1.x*o1.x + o1.y*o1.y;
            }
        }
#pragma unroll
        for (int v = 0; v < 4; v++) {
            ls[v] += __shfl_xor_sync(0xffffffffu, ls[v], 1);
            ls[v] += __shfl_xor_sync(0xffffffffu, ls[v], 2);
            lq[v] += __shfl_xor_sync(0xffffffffu, lq[v], 1);
            lq[v] += __shfl_xor_sync(0xffffffffu, lq[v], 2);
        }
        if ((lane & 3) == 0) {
            int wnIdx = wid >> 2;
#pragma unroll
            for (int v = 0; v < 4; v++) {
                int rl = wm + (v >> 1)*16 + (lane >> 2) + (v & 1)*8;
                s_s[wnIdx][rl] = ls[v]; s_q[wnIdx][rl] = lq[v];
            }
        }
        __syncthreads();
        if (tid < 128) {
            int c = blk_m*128 + tid, slice = bk*8 + blk_n;
            g_ps[c*1024 + slice] = s_s[0][tid] + s_s[1][tid];
            g_pq[c*1024 + slice] = s_q[0][tid] + s_q[1][tid];
        }
    }
}

// ---------------- 3: energy via tensor cores, tf32x3 (fp32-grade accuracy) ----------------
#define ESMEM ((2*128*36 + 2*32*132)*4)
__global__ void __launch_bounds__(256) k_energy_tc() {
    extern __shared__ float es[];
    float* ahi = es;
    float* alo = es + 128*36;
    float* bhi = es + 2*128*36;
    float* blo = bhi + 32*132;
    int tid = threadIdx.x, lane = tid & 31, wid = tid >> 5;
    int bk = blockIdx.z, m0 = blockIdx.x * 128, n0 = blockIdx.y * 128;
    const float* Qt = g_qt + ((size_t)bk*N_ + n0) * CQ_;
    const float* Kp = g_k + (size_t)bk * CQ_ * N_ + m0;
    int wm = (wid & 3) * 32, wn = (wid >> 2) * 64;
    float acc[2][8][4] = {};

    for (int c = 0; c < 2; c++) {
        if (c) __syncthreads();
        int dc = c * 32;
#pragma unroll
        for (int i = 0; i < 4; i++) {
            int f = tid + i*256, row = f >> 3, cg = f & 7;
            float4 v = *(const float4*)(Qt + (size_t)row*CQ_ + dc + cg*4);
            float4 h = make_float4(tf32r(v.x), tf32r(v.y), tf32r(v.z), tf32r(v.w));
            float4 l = make_float4(tf32r(v.x-h.x), tf32r(v.y-h.y), tf32r(v.z-h.z), tf32r(v.w-h.w));
            *(float4*)&ahi[row*36 + cg*4] = h;
            *(float4*)&alo[row*36 + cg*4] = l;
        }
#pragma unroll
        for (int i = 0; i < 4; i++) {
            int f = tid + i*256, row = f >> 5, mg = f & 31;
            float4 v = *(const float4*)(Kp + (size_t)(dc+row)*N_ + mg*4);
            float4 h = make_float4(tf32r(v.x), tf32r(v.y), tf32r(v.z), tf32r(v.w));
            float4 l = make_float4(tf32r(v.x-h.x), tf32r(v.y-h.y), tf32r(v.z-h.z), tf32r(v.w-h.w));
            *(float4*)&bhi[row*132 + mg*4] = h;
            *(float4*)&blo[row*132 + mg*4] = l;
        }
        __syncthreads();
#pragma unroll
        for (int p = 0; p < 3; p++) {
            const float* A  = (p == 2) ? alo : ahi;
            const float* Bz = (p == 1) ? blo : bhi;
#pragma unroll
            for (int ks = 0; ks < 4; ks++) {
                int k0 = ks*8 + (lane & 3);
                uint32_t af[2][4];
#pragma unroll
                for (int i = 0; i < 2; i++) {
                    int m = wm + i*16 + (lane >> 2);
                    af[i][0] = __float_as_uint(A[m*36 + k0]);
                    af[i][1] = __float_as_uint(A[(m+8)*36 + k0]);
                    af[i][2] = __float_as_uint(A[m*36 + k0 + 4]);
                    af[i][3] = __float_as_uint(A[(m+8)*36 + k0 + 4]);
                }
#pragma unroll
                for (int j = 0; j < 8; j++) {
                    int nc = wn + j*8 + (lane >> 2);
                    uint32_t b0 = __float_as_uint(Bz[k0*132 + nc]);
                    uint32_t b1 = __float_as_uint(Bz[(k0+4)*132 + nc]);
#pragma unroll
                    for (int i = 0; i < 2; i++)
                        asm volatile(
                            "mma.sync.aligned.m16n8k8.row.col.f32.tf32.tf32.f32 "
                            "{%0,%1,%2,%3}, {%4,%5,%6,%7}, {%8,%9}, {%0,%1,%2,%3};"
                            : "+f"(acc[i][j][0]), "+f"(acc[i][j][1]),
                              "+f"(acc[i][j][2]), "+f"(acc[i][j][3])
                            : "r"(af[i][0]), "r"(af[i][1]), "r"(af[i][2]), "r"(af[i][3]),
                              "r"(b0), "r"(b1));
                }
            }
        }
    }
    float* E = g_e + (size_t)bk * N_ * N_;
#pragma unroll
    for (int i = 0; i < 2; i++) {
        int row = n0 + wm + i*16 + (lane >> 2);
#pragma unroll
        for (int j = 0; j < 8; j++) {
            int col = m0 + wn + j*8 + 2*(lane & 3);
            *(float2*)&E[(size_t)row*N_ + col] = make_float2(acc[i][j][0], acc[i][j][1]);
            *(float2*)&E[(size_t)(row+8)*N_ + col] = make_float2(acc[i][j][2], acc[i][j][3]);
        }
    }
}

// ---------------- 4: softmax + k-renorm in place ----------------
__global__ void k_softmax() {
    int b = blockIdx.x >> 10, n = blockIdx.x & 1023;
    int tid = threadIdx.x, lane = tid & 31, wid = tid >> 5;
    __shared__ float wred[8][16], gmax[16], ginv[16];
    float vals[16][4];
#pragma unroll
    for (int k = 0; k < 16; k++) {
        const float* row = g_e + ((size_t)(b*K_+k)*N_ + n) * N_;
        float m = -1e30f;
#pragma unroll
        for (int j = 0; j < 4; j++) { vals[k][j] = row[tid + j*256]; m = fmaxf(m, vals[k][j]); }
#pragma unroll
        for (int o = 16; o; o >>= 1) m = fmaxf(m, __shfl_xor_sync(0xffffffffu, m, o));
        if (lane == 0) wred[wid][k] = m;
    }
    __syncthreads();
    if (tid < 16) {
        float m = -1e30f;
#pragma unroll
        for (int w = 0; w < 8; w++) m = fmaxf(m, wred[w][tid]);
        gmax[tid] = m;
    }
    __syncthreads();
#pragma unroll
    for (int k = 0; k < 16; k++) {
        float mk = gmax[k], s = 0.f;
#pragma unroll
        for (int j = 0; j < 4; j++) { vals[k][j] = __expf(vals[k][j] - mk); s += vals[k][j]; }
#pragma unroll
        for (int o = 16; o; o >>= 1) s += __shfl_xor_sync(0xffffffffu, s, o);
        if (lane == 0) wred[wid][k] = s;
    }
    __syncthreads();
    if (tid < 16) {
        float s = 0.f;
#pragma unroll
        for (int w = 0; w < 8; w++) s += wred[w][tid];
        ginv[tid] = 1.f / s;
    }
    __syncthreads();
    float asum[4] = {0.f, 0.f, 0.f, 0.f};
#pragma unroll
    for (int k = 0; k < 16; k++) {
        float inv = ginv[k];
#pragma unroll
        for (int j = 0; j < 4; j++) { vals[k][j] *= inv; asum[j] += vals[k][j]; }
    }
#pragma unroll
    for (int j = 0; j < 4; j++) asum[j] = 1.f / (1e-9f + asum[j]);
#pragma unroll
    for (int k = 0; k < 16; k++) {
        float* row = g_e + ((size_t)(b*K_+k)*N_ + n) * N_;
#pragma unroll
        for (int j = 0; j < 4; j++) row[tid + j*256] = vals[k][j] * asum[j];
    }
}

// ---------------- 6: BN final reduce ----------------
__global__ void k_bnred() {
    int c = blockIdx.x, tid = threadIdx.x;
    __shared__ float rs[256], rq[256];
    float s = 0.f, q = 0.f;
    for (int i = tid; i < 1024; i += 256) { s += g_ps[c*1024 + i]; q += g_pq[c*1024 + i]; }
    rs[tid] = s; rq[tid] = q;
    __syncthreads();
    for (int o = 128; o; o >>= 1) {
        if (tid < o) { rs[tid] += rs[tid+o]; rq[tid] += rq[tid+o]; }
        __syncthreads();
    }
    if (tid == 0) {
        const float inv = 1.f / (float)(B_*N_*K_);
        float mean = rs[0] * inv;
        g_mean[c] = mean;
        g_rstd[c] = rsqrtf(rq[0]*inv - mean*mean + 1e-5f);
    }
}

// ---------------- 7: out = x + relu(BN(t)), back to [B,C,N,K] ----------------
__global__ void k_final(const float* __restrict__ x, const float* __restrict__ gamma,
                        const float* __restrict__ beta, float* __restrict__ out) {
    __shared__ float s[16][65];
    int b = blockIdx.z, c = blockIdx.y, n0 = blockIdx.x * 64;
    int tid = threadIdx.x;
    float mean = g_mean[c], rstd = g_rstd[c], ga = gamma[c], be = beta[c];
    int nn = tid & 63, kb = tid >> 6;
#pragma unroll
    for (int r = 0; r < 4; r++) {
        int kq = kb + r*4;
        s[kq][nn] = g_t[((size_t)(b*K_+kq)*C_ + c)*N_ + n0 + nn];
    }
    __syncthreads();
    const float* xs = x   + ((size_t)(b*C_+c)*N_ + n0) * K_;
    float*       os = out + ((size_t)(b*C_+c)*N_ + n0) * K_;
#pragma unroll
    for (int r = 0; r < 4; r++) {
        int i = tid + r*256;
        float v = fmaf((s[i & 15][i >> 4] - mean) * rstd, ga, be);
        os[i] = xs[i] + fmaxf(v, 0.f);
    }
}

// ---------------- launch ----------------
extern "C" void kernel_launch(void* const* d_in, const int* in_sizes, int n_in,
                              void* d_out, int out_size) {
    const float* x     = (const float*)d_in[0];
    const float* q_w   = (const float*)d_in[1];
    const float* k_w   = (const float*)d_in[2];
    const float* v_w   = (const float*)d_in[3];
    const float* v_b   = (const float*)d_in[4];
    const float* t_w   = (const float*)d_in[5];
    const float* t_b   = (const float*)d_in[6];
    const float* gamma = (const float*)d_in[7];
    const float* beta  = (const float*)d_in[8];
    float* out = (float*)d_out;

    cudaFuncSetAttribute(k_mma<0>, cudaFuncAttributeMaxDynamicSharedMemorySize, SMEM_MMA);
    cudaFuncSetAttribute(k_mma<1>, cudaFuncAttributeMaxDynamicSharedMemorySize, SMEM_MMA);
    cudaFuncSetAttribute(k_energy_tc, cudaFuncAttributeMaxDynamicSharedMemorySize, ESMEM);

    k_prep     <<<MALL, 256>>>(q_w, k_w, v_w, v_b, t_w, t_b);
    k_xpose    <<<dim3(N_/8, C_/32, B_), 256>>>(x);
    k_stage2qk <<<dim3(N_/64, 2, BK_), 256>>>();
    k_mma<0>   <<<dim3(32, 1, BK_), 256, SMEM_MMA>>>();
    k_energy_tc<<<dim3(8, 8, BK_), 256, ESMEM>>>();
    k_softmax  <<<B_*N_, 256>>>();
    k_mma<1>   <<<dim3(16, 1, BK_), 256, SMEM_MMA>>>();
    k_bnred    <<<C_, 256>>>();
    k_final    <<<dim3(N_/64, C_, B_), 256>>>(x, gamma, beta, out);
}

// round 16
// speedup vs baseline: 2.2765x; 1.0688x over previous
#include <cuda_runtime.h>
#include <cstdint>

#define B_ 8
#define C_ 256
#define N_ 1024
#define K_ 16
#define CQ_ 64
#define BK_ (B_*K_)
#define MALL 640
#define NELEM_T ((size_t)BK_*C_*N_)

// ---------------- scratch ----------------
__device__ float g_wall[MALL*C_];
__device__ float g_ball[MALL];
__device__ float g_xt[(size_t)BK_*N_*C_];   // x transposed [B,K,N,C]
__device__ float g_qt[(size_t)BK_*N_*CQ_];  // Q transposed [bk][n][cq]
__device__ float g_k[(size_t)BK_*CQ_*N_];   // [bk][cq][n]
__device__ float g_u[NELEM_T];              // [bk][c][n]
__device__ float g_t1[NELEM_T];
__device__ float g_t[NELEM_T];
__device__ float g_e[(size_t)BK_*N_*N_];    // energy/attn [bk][n][m]
__device__ float g_ps[256*1024], g_pq[256*1024];  // BN partial sums [c][slice]
__device__ float g_mean[C_], g_rstd[C_];

__device__ __forceinline__ float tf32r(float x) {
    float r; asm("cvt.rna.tf32.f32 %0, %1;" : "=f"(r) : "f"(x)); return r;
}
__device__ __forceinline__ void cpa16(uint32_t dst, const void* src) {
    asm volatile("cp.async.cg.shared.global [%0], [%1], 16;" :: "r"(dst), "l"(src));
}
#define CP_COMMIT() asm volatile("cp.async.commit_group;" ::: "memory")
#define CP_WAIT(n)  asm volatile("cp.async.wait_group %0;" :: "n"(n) : "memory")

// ---------------- 0: fold weights ----------------
__global__ void k_prep(const float* __restrict__ qw, const float* __restrict__ kw,
                       const float* __restrict__ vw, const float* __restrict__ vb,
                       const float* __restrict__ tw, const float* __restrict__ tb) {
    int r = blockIdx.x, c = threadIdx.x;
    if (r < 64) { g_wall[r*C_+c] = qw[r*C_+c]; if (c==0) g_ball[r] = 0.f; }
    else if (r < 128) { g_wall[r*C_+c] = kw[(r-64)*C_+c]; if (c==0) g_ball[r] = 0.f; }
    else if (r < 384) {
        int o = r - 128; float s = 0.f;
        for (int c2 = 0; c2 < C_; c2++) s = fmaf(tw[o*C_+c2], vw[c2*C_+c], s);
        g_wall[r*C_+c] = s;
        if (c == 0) {
            float sb = 0.f;
            for (int c2 = 0; c2 < C_; c2++) sb = fmaf(tw[o*C_+c2], vb[c2], sb);
            g_ball[r] = sb;
        }
    } else { int o = r - 384; g_wall[r*C_+c] = tw[o*C_+c]; if (c==0) g_ball[r] = tb[o]; }
}

// ---------------- 1: x [B,C,N,K] -> xt [B,K,N,C] ----------------
__global__ void k_xpose(const float* __restrict__ x) {
    __shared__ float s[32][132];
    int b = blockIdx.z, c0 = blockIdx.y * 32, n0 = blockIdx.x * 8;
    int tid = threadIdx.x;
    {
        int cl = tid >> 3, f = tid & 7;
        const float* src = x + ((size_t)(b*C_ + c0 + cl)*N_ + n0) * K_;
#pragma unroll
        for (int i = 0; i < 4; i++) {
            int j = (f + i*8) * 4;
            *(float4*)&s[cl][j] = *(const float4*)(src + j);
        }
    }
    __syncthreads();
    int q2 = tid >> 1, h = tid & 1;
    int nl = q2 & 7, kk = q2 >> 3;
    int p = nl*16 + kk;
    float* dst = g_xt + ((size_t)((b*K_+kk)*N_) + n0 + nl)*C_ + c0 + h*16;
#pragma unroll
    for (int q = 0; q < 4; q++) {
        int cc = h*16 + q*4;
        *(float4*)(dst + q*4) = make_float4(s[cc][p], s[cc+1][p], s[cc+2][p], s[cc+3][p]);
    }
}

#define FMA16(acc, a, bv)                                  \
    acc[0][0]=fmaf(a.x,bv.x,acc[0][0]); acc[0][1]=fmaf(a.x,bv.y,acc[0][1]); \
    acc[0][2]=fmaf(a.x,bv.z,acc[0][2]); acc[0][3]=fmaf(a.x,bv.w,acc[0][3]); \
    acc[1][0]=fmaf(a.y,bv.x,acc[1][0]); acc[1][1]=fmaf(a.y,bv.y,acc[1][1]); \
    acc[1][2]=fmaf(a.y,bv.z,acc[1][2]); acc[1][3]=fmaf(a.y,bv.w,acc[1][3]); \
    acc[2][0]=fmaf(a.z,bv.x,acc[2][0]); acc[2][1]=fmaf(a.z,bv.y,acc[2][1]); \
    acc[2][2]=fmaf(a.z,bv.z,acc[2][2]); acc[2][3]=fmaf(a.z,bv.w,acc[2][3]); \
    acc[3][0]=fmaf(a.w,bv.x,acc[3][0]); acc[3][1]=fmaf(a.w,bv.y,acc[3][1]); \
    acc[3][2]=fmaf(a.w,bv.z,acc[3][2]); acc[3][3]=fmaf(a.w,bv.w,acc[3][3]);

// ---------------- 2a: q,k GEMM (fp32 SIMT). q written transposed [n][cq]. ----------------
__global__ void k_stage2qk() {
    __shared__ float As[16][68], Bs[16][68];
    __shared__ float st[64][68];
    int bk = blockIdx.z;
    int m0 = blockIdx.y * 64, n0 = blockIdx.x * 64;
    const float* X = g_xt + (size_t)bk * N_ * C_;
    int tid = threadIdx.x, tx = tid & 15, ty = tid >> 4;
    int amm = tid >> 2, acg = (tid & 3) * 4;
    float acc[4][4] = {};
    for (int kc = 0; kc < C_; kc += 16) {
        float4 av = *(const float4*)&g_wall[(m0+amm)*C_ + kc + acg];
        As[acg][amm]=av.x; As[acg+1][amm]=av.y; As[acg+2][amm]=av.z; As[acg+3][amm]=av.w;
        float4 bv = *(const float4*)&X[(size_t)(n0+amm)*C_ + kc + acg];
        Bs[acg][amm]=bv.x; Bs[acg+1][amm]=bv.y; Bs[acg+2][amm]=bv.z; Bs[acg+3][amm]=bv.w;
        __syncthreads();
#pragma unroll
        for (int kk = 0; kk < 16; kk++) {
            float4 a  = *(const float4*)&As[kk][ty*4];
            float4 b2 = *(const float4*)&Bs[kk][tx*4];
            FMA16(acc, a, b2)
        }
        __syncthreads();
    }
    if (m0 == 0) {
#pragma unroll
        for (int i = 0; i < 4; i++)
#pragma unroll
            for (int j = 0; j < 4; j++)
                st[tx*4+j][ty*4+i] = acc[i][j];
        __syncthreads();
        int nn = tid >> 2;
        float* dst = g_qt + ((size_t)bk*N_ + n0 + nn) * CQ_;
#pragma unroll
        for (int q = 0; q < 4; q++) {
            int f = (tid & 3) + q*4;
            *(float4*)(dst + f*4) = *(const float4*)&st[nn][f*4];
        }
    } else {
#pragma unroll
        for (int i = 0; i < 4; i++) {
            int r = m0 + ty*4 + i;
            float* dst = g_k + ((size_t)bk*CQ_ + (r-64))*N_;
            *(float4*)&dst[n0 + tx*4] = make_float4(acc[i][0], acc[i][1], acc[i][2], acc[i][3]);
        }
    }
}

// ---------------- mma.sync tf32 GEMM, cp.async 3-stage pipeline ----------------
// MODE 0 = u/t1 conv, MODE 1 = xr (+BN partials). HW truncates fp32->tf32 (no cvt).
#define SAPITCH 36
#define A_FL (128*36)            // 4608 floats per A stage
#define B_FL 4608                // max(128*36, 32*132)
#define STG_FL (A_FL + B_FL)     // 9216 floats
#define SMEM_MMA (3*STG_FL*4)    // 110592 bytes

template<int MODE>
__global__ void __launch_bounds__(256) k_mma() {
    extern __shared__ float smf[];
    uint32_t smu = (uint32_t)__cvta_generic_to_shared(smf);
    __shared__ float s_s[2][128], s_q[2][128];
    int tid = threadIdx.x, lane = tid & 31, wid = tid >> 5;
    int bk = blockIdx.z;
    int blk_m, blk_n, NCH, lda;
    const float *Ap, *Bp;
    if (MODE == 0) {
        blk_m = blockIdx.x & 3; blk_n = blockIdx.x >> 2; NCH = C_/32;
        Ap = g_wall + (size_t)(128 + blk_m*128) * C_;                lda = C_;
        Bp = g_xt + (size_t)bk*N_*C_ + (size_t)(blk_n*128)*C_;
    } else {
        blk_m = blockIdx.x & 1; blk_n = blockIdx.x >> 1; NCH = N_/32;
        Ap = g_u + ((size_t)bk*C_ + blk_m*128)*N_;                   lda = N_;
        Bp = g_e + (size_t)bk*N_*N_;
    }
    int m0col = blk_n * 128;

    auto loadStage = [&](int kc, int st) {
        uint32_t ab = smu + st*STG_FL*4;
        uint32_t bb = ab + A_FL*4;
#pragma unroll
        for (int i = 0; i < 4; i++) {
            int f = tid + i*256, row = f >> 3, cg = f & 7;
            cpa16(ab + (row*SAPITCH + cg*4)*4, Ap + (size_t)row*lda + kc + cg*4);
        }
        if (MODE == 0) {
#pragma unroll
            for (int i = 0; i < 4; i++) {
                int f = tid + i*256, row = f >> 3, cg = f & 7;
                cpa16(bb + (row*SAPITCH + cg*4)*4, Bp + (size_t)row*C_ + kc + cg*4);
            }
        } else {
#pragma unroll
            for (int i = 0; i < 4; i++) {
                int f = tid + i*256, nr = f >> 5, mg = f & 31;
                cpa16(bb + (nr*132 + mg*4)*4, Bp + (size_t)(kc+nr)*N_ + m0col + mg*4);
            }
        }
    };

    int wm = (wid & 3) * 32, wn = (wid >> 2) * 64;
    float acc[2][8][4] = {};

    loadStage(0, 0); CP_COMMIT();
    loadStage(32, 1); CP_COMMIT();

    for (int c = 0; c < NCH; c++) {
        if (c == NCH-1) { CP_WAIT(0); } else { CP_WAIT(1); }
        __syncthreads();
        if (c + 2 < NCH) { loadStage((c+2)*32, (c+2)%3); CP_COMMIT(); }
        const float* A  = smf + (c%3)*STG_FL;
        const float* Bz = A + A_FL;
#pragma unroll
        for (int ks = 0; ks < 4; ks++) {
            int k0 = ks*8 + (lane & 3);
            uint32_t af[2][4];
#pragma unroll
            for (int i = 0; i < 2; i++) {
                int m = wm + i*16 + (lane >> 2);
                af[i][0] = __float_as_uint(A[m*SAPITCH + k0]);
                af[i][1] = __float_as_uint(A[(m+8)*SAPITCH + k0]);
                af[i][2] = __float_as_uint(A[m*SAPITCH + k0 + 4]);
                af[i][3] = __float_as_uint(A[(m+8)*SAPITCH + k0 + 4]);
            }
#pragma unroll
            for (int j = 0; j < 8; j++) {
                int nc = wn + j*8 + (lane >> 2);
                uint32_t b0, b1;
                if (MODE == 0) {
                    b0 = __float_as_uint(Bz[nc*SAPITCH + k0]);
                    b1 = __float_as_uint(Bz[nc*SAPITCH + k0 + 4]);
                } else {
                    b0 = __float_as_uint(Bz[k0*132 + nc]);
                    b1 = __float_as_uint(Bz[(k0+4)*132 + nc]);
                }
#pragma unroll
                for (int i = 0; i < 2; i++)
                    asm volatile(
                        "mma.sync.aligned.m16n8k8.row.col.f32.tf32.tf32.f32 "
                        "{%0,%1,%2,%3}, {%4,%5,%6,%7}, {%8,%9}, {%0,%1,%2,%3};"
                        : "+f"(acc[i][j][0]), "+f"(acc[i][j][1]),
                          "+f"(acc[i][j][2]), "+f"(acc[i][j][3])
                        : "r"(af[i][0]), "r"(af[i][1]), "r"(af[i][2]), "r"(af[i][3]),
                          "r"(b0), "r"(b1));
            }
        }
    }

    // ---- epilogue ----
    if (MODE == 0) {
        int arow0 = 128 + blk_m*128;
        float* dstb = (arow0 < 384) ? g_u  + ((size_t)bk*C_ + (arow0-128))*N_
                                    : g_t1 + ((size_t)bk*C_ + (arow0-384))*N_;
#pragma unroll
        for (int i = 0; i < 2; i++) {
            int r0 = wm + i*16 + (lane >> 2);
            float bv0 = g_ball[arow0 + r0], bv1 = g_ball[arow0 + r0 + 8];
#pragma unroll
            for (int j = 0; j < 8; j++) {
                int col = m0col + wn + j*8 + 2*(lane & 3);
                *(float2*)&dstb[(size_t)r0*N_ + col] =
                    make_float2(acc[i][j][0] + bv0, acc[i][j][1] + bv0);
                *(float2*)&dstb[(size_t)(r0+8)*N_ + col] =
                    make_float2(acc[i][j][2] + bv1, acc[i][j][3] + bv1);
            }
        }
    } else {
        float ls[4] = {0,0,0,0}, lq[4] = {0,0,0,0};
#pragma unroll
        for (int i = 0; i < 2; i++) {
            int r0 = blk_m*128 + wm + i*16 + (lane >> 2);
#pragma unroll
            for (int j = 0; j < 8; j++) {
                int col = m0col + wn + j*8 + 2*(lane & 3);
                size_t i0 = ((size_t)bk*C_ + r0)*N_ + col;
                size_t i1 = i0 + (size_t)8*N_;
                float2 ta = *(const float2*)&g_t1[i0];
                float2 tb = *(const float2*)&g_t1[i1];
                float2 o0 = make_float2(ta.x - acc[i][j][0], ta.y - acc[i][j][1]);
                float2 o1 = make_float2(tb.x - acc[i][j][2], tb.y - acc[i][j][3]);
                *(float2*)&g_t[i0] = o0;
                *(float2*)&g_t[i1] = o1;
                ls[i*2]   += o0.x + o0.y; lq[i*2]   += o0.x*o0.x + o0.y*o0.y;
                ls[i*2+1] += o1.x + o1.y; lq[i*2+1] += o1.x*o1.x + o1.y*o1.y;
            }
        }
#pragma unroll
        for (int v = 0; v < 4; v++) {
            ls[v] += __shfl_xor_sync(0xffffffffu, ls[v], 1);
            ls[v] += __shfl_xor_sync(0xffffffffu, ls[v], 2);
            lq[v] += __shfl_xor_sync(0xffffffffu, lq[v], 1);
            lq[v] += __shfl_xor_sync(0xffffffffu, lq[v], 2);
        }
        if ((lane & 3) == 0) {
            int wnIdx = wid >> 2;
#pragma unroll
            for (int v = 0; v < 4; v++) {
                int rl = wm + (v >> 1)*16 + (lane >> 2) + (v & 1)*8;
                s_s[wnIdx][rl] = ls[v]; s_q[wnIdx][rl] = lq[v];
            }
        }
        __syncthreads();
        if (tid < 128) {
            int c = blk_m*128 + tid, slice = bk*8 + blk_n;
            g_ps[c*1024 + slice] = s_s[0][tid] + s_s[1][tid];
            g_pq[c*1024 + slice] = s_q[0][tid] + s_q[1][tid];
        }
    }
}

// ---------------- 3: energy via tensor cores, tf32x3 (fp32-grade accuracy) ----------------
#define ESMEM ((2*128*36 + 2*32*132)*4)
__global__ void __launch_bounds__(256) k_energy_tc() {
    extern __shared__ float es[];
    float* ahi = es;
    float* alo = es + 128*36;
    float* bhi = es + 2*128*36;
    float* blo = bhi + 32*132;
    int tid = threadIdx.x, lane = tid & 31, wid = tid >> 5;
    int bk = blockIdx.z, m0 = blockIdx.x * 128, n0 = blockIdx.y * 128;
    const float* Qt = g_qt + ((size_t)bk*N_ + n0) * CQ_;
    const float* Kp = g_k + (size_t)bk * CQ_ * N_ + m0;
    int wm = (wid & 3) * 32, wn = (wid >> 2) * 64;
    float acc[2][8][4] = {};

    for (int c = 0; c < 2; c++) {
        if (c) __syncthreads();
        int dc = c * 32;
#pragma unroll
        for (int i = 0; i < 4; i++) {
            int f = tid + i*256, row = f >> 3, cg = f & 7;
            float4 v = *(const float4*)(Qt + (size_t)row*CQ_ + dc + cg*4);
            float4 h = make_float4(tf32r(v.x), tf32r(v.y), tf32r(v.z), tf32r(v.w));
            float4 l = make_float4(tf32r(v.x-h.x), tf32r(v.y-h.y), tf32r(v.z-h.z), tf32r(v.w-h.w));
            *(float4*)&ahi[row*36 + cg*4] = h;
            *(float4*)&alo[row*36 + cg*4] = l;
        }
#pragma unroll
        for (int i = 0; i < 4; i++) {
            int f = tid + i*256, row = f >> 5, mg = f & 31;
            float4 v = *(const float4*)(Kp + (size_t)(dc+row)*N_ + mg*4);
            float4 h = make_float4(tf32r(v.x), tf32r(v.y), tf32r(v.z), tf32r(v.w));
            float4 l = make_float4(tf32r(v.x-h.x), tf32r(v.y-h.y), tf32r(v.z-h.z), tf32r(v.w-h.w));
            *(float4*)&bhi[row*132 + mg*4] = h;
            *(float4*)&blo[row*132 + mg*4] = l;
        }
        __syncthreads();
#pragma unroll
        for (int p = 0; p < 3; p++) {
            const float* A  = (p == 2) ? alo : ahi;
            const float* Bz = (p == 1) ? blo : bhi;
#pragma unroll
            for (int ks = 0; ks < 4; ks++) {
                int k0 = ks*8 + (lane & 3);
                uint32_t af[2][4];
#pragma unroll
                for (int i = 0; i < 2; i++) {
                    int m = wm + i*16 + (lane >> 2);
                    af[i][0] = __float_as_uint(A[m*36 + k0]);
                    af[i][1] = __float_as_uint(A[(m+8)*36 + k0]);
                    af[i][2] = __float_as_uint(A[m*36 + k0 + 4]);
                    af[i][3] = __float_as_uint(A[(m+8)*36 + k0 + 4]);
                }
#pragma unroll
                for (int j = 0; j < 8; j++) {
                    int nc = wn + j*8 + (lane >> 2);
                    uint32_t b0 = __float_as_uint(Bz[k0*132 + nc]);
                    uint32_t b1 = __float_as_uint(Bz[(k0+4)*132 + nc]);
#pragma unroll
                    for (int i = 0; i < 2; i++)
                        asm volatile(
                            "mma.sync.aligned.m16n8k8.row.col.f32.tf32.tf32.f32 "
                            "{%0,%1,%2,%3}, {%4,%5,%6,%7}, {%8,%9}, {%0,%1,%2,%3};"
                            : "+f"(acc[i][j][0]), "+f"(acc[i][j][1]),
                              "+f"(acc[i][j][2]), "+f"(acc[i][j][3])
                            : "r"(af[i][0]), "r"(af[i][1]), "r"(af[i][2]), "r"(af[i][3]),
                              "r"(b0), "r"(b1));
                }
            }
        }
    }
    float* E = g_e + (size_t)bk * N_ * N_;
#pragma unroll
    for (int i = 0; i < 2; i++) {
        int row = n0 + wm + i*16 + (lane >> 2);
#pragma unroll
        for (int j = 0; j < 8; j++) {
            int col = m0 + wn + j*8 + 2*(lane & 3);
            *(float2*)&E[(size_t)row*N_ + col] = make_float2(acc[i][j][0], acc[i][j][1]);
            *(float2*)&E[(size_t)(row+8)*N_ + col] = make_float2(acc[i][j][2], acc[i][j][3]);
        }
    }
}

// ---------------- 4: softmax + k-renorm in place (float4) ----------------
__global__ void k_softmax() {
    int b = blockIdx.x >> 10, n = blockIdx.x & 1023;
    int tid = threadIdx.x, lane = tid & 31, wid = tid >> 5;
    __shared__ float wred[8][16], gmax[16], ginv[16];
    float4 vals[16];
#pragma unroll
    for (int k = 0; k < 16; k++) {
        const float* row = g_e + ((size_t)(b*K_+k)*N_ + n) * N_;
        float4 v = *(const float4*)&row[tid*4];
        vals[k] = v;
        float m = fmaxf(fmaxf(v.x, v.y), fmaxf(v.z, v.w));
#pragma unroll
        for (int o = 16; o; o >>= 1) m = fmaxf(m, __shfl_xor_sync(0xffffffffu, m, o));
        if (lane == 0) wred[wid][k] = m;
    }
    __syncthreads();
    if (tid < 16) {
        float m = -1e30f;
#pragma unroll
        for (int w = 0; w < 8; w++) m = fmaxf(m, wred[w][tid]);
        gmax[tid] = m;
    }
    __syncthreads();
#pragma unroll
    for (int k = 0; k < 16; k++) {
        float mk = gmax[k];
        vals[k].x = __expf(vals[k].x - mk); vals[k].y = __expf(vals[k].y - mk);
        vals[k].z = __expf(vals[k].z - mk); vals[k].w = __expf(vals[k].w - mk);
        float s = vals[k].x + vals[k].y + vals[k].z + vals[k].w;
#pragma unroll
        for (int o = 16; o; o >>= 1) s += __shfl_xor_sync(0xffffffffu, s, o);
        if (lane == 0) wred[wid][k] = s;
    }
    __syncthreads();
    if (tid < 16) {
        float s = 0.f;
#pragma unroll
        for (int w = 0; w < 8; w++) s += wred[w][tid];
        ginv[tid] = 1.f / s;
    }
    __syncthreads();
    float4 asum = make_float4(0.f, 0.f, 0.f, 0.f);
#pragma unroll
    for (int k = 0; k < 16; k++) {
        float inv = ginv[k];
        vals[k].x *= inv; vals[k].y *= inv; vals[k].z *= inv; vals[k].w *= inv;
        asum.x += vals[k].x; asum.y += vals[k].y; asum.z += vals[k].z; asum.w += vals[k].w;
    }
    asum.x = 1.f/(1e-9f+asum.x); asum.y = 1.f/(1e-9f+asum.y);
    asum.z = 1.f/(1e-9f+asum.z); asum.w = 1.f/(1e-9f+asum.w);
#pragma unroll
    for (int k = 0; k < 16; k++) {
        float* row = g_e + ((size_t)(b*K_+k)*N_ + n) * N_;
        *(float4*)&row[tid*4] = make_float4(vals[k].x*asum.x, vals[k].y*asum.y,
                                            vals[k].z*asum.z, vals[k].w*asum.w);
    }
}

// ---------------- 6: BN final reduce ----------------
__global__ void k_bnred() {
    int c = blockIdx.x, tid = threadIdx.x;
    __shared__ float rs[256], rq[256];
    float s = 0.f, q = 0.f;
    for (int i = tid; i < 1024; i += 256) { s += g_ps[c*1024 + i]; q += g_pq[c*1024 + i]; }
    rs[tid] = s; rq[tid] = q;
    __syncthreads();
    for (int o = 128; o; o >>= 1) {
        if (tid < o) { rs[tid] += rs[tid+o]; rq[tid] += rq[tid+o]; }
        __syncthreads();
    }
    if (tid == 0) {
        const float inv = 1.f / (float)(B_*N_*K_);
        float mean = rs[0] * inv;
        g_mean[c] = mean;
        g_rstd[c] = rsqrtf(rq[0]*inv - mean*mean + 1e-5f);
    }
}

// ---------------- 7: out = x + relu(BN(t)), back to [B,C,N,K] ----------------
__global__ void k_final(const float* __restrict__ x, const float* __restrict__ gamma,
                        const float* __restrict__ beta, float* __restrict__ out) {
    __shared__ float s[16][65];
    int b = blockIdx.z, c = blockIdx.y, n0 = blockIdx.x * 64;
    int tid = threadIdx.x;
    float mean = g_mean[c], rstd = g_rstd[c], ga = gamma[c], be = beta[c];
    int nn = tid & 63, kb = tid >> 6;
#pragma unroll
    for (int r = 0; r < 4; r++) {
        int kq = kb + r*4;
        s[kq][nn] = g_t[((size_t)(b*K_+kq)*C_ + c)*N_ + n0 + nn];
    }
    __syncthreads();
    const float* xs = x   + ((size_t)(b*C_+c)*N_ + n0) * K_;
    float*       os = out + ((size_t)(b*C_+c)*N_ + n0) * K_;
#pragma unroll
    for (int r = 0; r < 4; r++) {
        int i = tid + r*256;
        float v = fmaf((s[i & 15][i >> 4] - mean) * rstd, ga, be);
        os[i] = xs[i] + fmaxf(v, 0.f);
    }
}

// ---------------- launch ----------------
extern "C" void kernel_launch(void* const* d_in, const int* in_sizes, int n_in,
                              void* d_out, int out_size) {
    const float* x     = (const float*)d_in[0];
    const float* q_w   = (const float*)d_in[1];
    const float* k_w   = (const float*)d_in[2];
    const float* v_w   = (const float*)d_in[3];
    const float* v_b   = (const float*)d_in[4];
    const float* t_w   = (const float*)d_in[5];
    const float* t_b   = (const float*)d_in[6];
    const float* gamma = (const float*)d_in[7];
    const float* beta  = (const float*)d_in[8];
    float* out = (float*)d_out;

    cudaFuncSetAttribute(k_mma<0>, cudaFuncAttributeMaxDynamicSharedMemorySize, SMEM_MMA);
    cudaFuncSetAttribute(k_mma<1>, cudaFuncAttributeMaxDynamicSharedMemorySize, SMEM_MMA);
    cudaFuncSetAttribute(k_energy_tc, cudaFuncAttributeMaxDynamicSharedMemorySize, ESMEM);

    k_prep     <<<MALL, 256>>>(q_w, k_w, v_w, v_b, t_w, t_b);
    k_xpose    <<<dim3(N_/8, C_/32, B_), 256>>>(x);
    k_stage2qk <<<dim3(N_/64, 2, BK_), 256>>>();
    k_mma<0>   <<<dim3(32, 1, BK_), 256, SMEM_MMA>>>();
    k_energy_tc<<<dim3(8, 8, BK_), 256, ESMEM>>>();
    k_softmax  <<<B_*N_, 256>>>();
    k_mma<1>   <<<dim3(16, 1, BK_), 256, SMEM_MMA>>>();
    k_bnred    <<<C_, 256>>>();
    k_final    <<<dim3(N_/64, C_, B_), 256>>>(x, gamma, beta, out);
}